// round 1
// baseline (speedup 1.0000x reference)
#include <cuda_runtime.h>

// Problem constants
#define BATCH 8
#define CIN   64
#define COUT  64
#define HH    112
#define WW    112
#define HWSZ  (HH*WW)

// Tiling
#define TH 16           // output rows per CTA
#define TW 16           // output cols per CTA
#define IN_H 18         // input tile rows  (TH + 2)
#define IN_W 18         // input tile cols  (TW + 2)
#define IN_STRIDE 18
#define NTHREADS 256

__global__ __launch_bounds__(NTHREADS, 2)
void rconv2d_kernel(const float* __restrict__ x,
                    const float* __restrict__ w,
                    const int*   __restrict__ mask,
                    float*       __restrict__ out)
{
    // double-buffered: input tile (18x18) + per-channel weights (64 o x 9 taps)
    __shared__ float s_in[2][IN_H * IN_STRIDE];
    __shared__ float s_w[2][COUT * 9];

    const int tid   = threadIdx.x;
    const int o_grp = tid >> 5;          // 0..7  -> output channels o_grp*8 .. +7
    const int lane  = tid & 31;
    const int row   = lane >> 1;         // 0..15 (output row within tile)
    const int x0    = (lane & 1) * 8;    // 0 or 8 (start col within tile)

    const int gx0 = blockIdx.x * TW;
    const int gy0 = blockIdx.y * TH;
    const int b   = blockIdx.z;

    const int y = gy0 + row;             // global output row for this thread

    // per-position masked tap index (kh*3+kw), one per output position
    int m[8];
    #pragma unroll
    for (int p = 0; p < 8; p++)
        m[p] = mask[y * WW + gx0 + x0 + p];

    float acc[8][8];                     // [o][p]
    #pragma unroll
    for (int o = 0; o < 8; o++)
        #pragma unroll
        for (int p = 0; p < 8; p++)
            acc[o][p] = 0.0f;

    const float* xb = x + (size_t)b * CIN * HWSZ;

    // loader: channel c -> smem buffer buf (input tile with zero halo + weights)
    auto load_ch = [&](int c, int buf) {
        const float* xc = xb + c * HWSZ;
        #pragma unroll
        for (int i = tid; i < IN_H * IN_W; i += NTHREADS) {
            int r  = i / IN_W;
            int cc = i - r * IN_W;
            int gy = gy0 - 1 + r;
            int gx = gx0 - 1 + cc;
            float v = 0.0f;
            if (gy >= 0 && gy < HH && gx >= 0 && gx < WW)
                v = xc[gy * WW + gx];
            s_in[buf][r * IN_STRIDE + cc] = v;
        }
        #pragma unroll
        for (int i = tid; i < COUT * 9; i += NTHREADS) {
            int o = i / 9;
            int t = i - o * 9;
            s_w[buf][i] = w[(o * CIN + c) * 9 + t];
        }
    };

    load_ch(0, 0);
    __syncthreads();

    int buf = 0;
    for (int c = 0; c < CIN; c++) {
        if (c + 1 < CIN) load_ch(c + 1, buf ^ 1);  // prefetch overlaps compute

        // cache 3 rows x 10 cols of the input tile in registers
        float in[3][10];
        #pragma unroll
        for (int kh = 0; kh < 3; kh++)
            #pragma unroll
            for (int j = 0; j < 10; j++)
                in[kh][j] = s_in[buf][(row + kh) * IN_STRIDE + x0 + j];

        const float* ws = s_w[buf] + o_grp * 8 * 9;

        #pragma unroll
        for (int t = 0; t < 9; t++) {
            const int kh = t / 3;
            const int kw = t - kh * 3;
            // masked input values for the 8 positions (ALU pipe, overlaps FFMA)
            float val[8];
            #pragma unroll
            for (int p = 0; p < 8; p++)
                val[p] = (m[p] == t) ? 0.0f : in[kh][p + kw];
            #pragma unroll
            for (int o = 0; o < 8; o++) {
                const float wv = ws[o * 9 + t];   // warp-uniform -> LDS broadcast
                #pragma unroll
                for (int p = 0; p < 8; p++)
                    acc[o][p] += val[p] * wv;
            }
        }
        __syncthreads();
        buf ^= 1;
    }

    // write 8 o x 8 contiguous x as 2x float4 per o (16B aligned: x0 % 8 == 0)
    const int o_base = o_grp * 8;
    #pragma unroll
    for (int o = 0; o < 8; o++) {
        float* dst = out + ((((size_t)b * COUT + o_base + o) * HH + y) * WW + gx0 + x0);
        float4 v0 = make_float4(acc[o][0], acc[o][1], acc[o][2], acc[o][3]);
        float4 v1 = make_float4(acc[o][4], acc[o][5], acc[o][6], acc[o][7]);
        reinterpret_cast<float4*>(dst)[0] = v0;
        reinterpret_cast<float4*>(dst)[1] = v1;
    }
}

extern "C" void kernel_launch(void* const* d_in, const int* in_sizes, int n_in,
                              void* d_out, int out_size)
{
    (void)in_sizes; (void)n_in; (void)out_size;
    const float* x    = (const float*)d_in[0];
    const float* w    = (const float*)d_in[1];
    const int*   mask = (const int*)d_in[2];
    float*       out  = (float*)d_out;

    dim3 grid(WW / TW, HH / TH, BATCH);   // 7 x 7 x 8 = 392 CTAs
    rconv2d_kernel<<<grid, NTHREADS>>>(x, w, mask, out);
}